// round 15
// baseline (speedup 1.0000x reference)
#include <cuda_runtime.h>
#include <math.h>
#include <float.h>

#define Bsz 2
#define Mdim 2048
#define Ndim 2048
#define Kk 32
#define Gg 60

__device__ int   g_nn[Bsz * Mdim];
__device__ float g_sc[(size_t)Bsz * Mdim * Ndim];   // 33.5 MB score buffer (L2-resident)
__device__ float g_qs[Bsz * Mdim * 32];
__device__ float g_kt[Bsz * Ndim * 32];
__device__ float g_vt[Bsz * Ndim * 32];
__device__ float g_x [Bsz * Mdim * 32];
__device__ float g_attn[Bsz * 32 * Mdim];
__device__ float g_h[Bsz * 64 * Mdim];
__device__ float g_mean[Bsz * 64];
__device__ float g_istd[Bsz * 64];

__device__ __forceinline__ unsigned ordf(float f) {
    unsigned u = __float_as_uint(f);
    return (u & 0x80000000u) ? ~u : (u | 0x80000000u);
}
__device__ __forceinline__ void ins4(float v, int n, float tv[4], int ti[4]) {
    if (v > tv[3]) {
        if (v > tv[1]) {
            if (v > tv[0]) { tv[3]=tv[2];ti[3]=ti[2]; tv[2]=tv[1];ti[2]=ti[1]; tv[1]=tv[0];ti[1]=ti[0]; tv[0]=v;ti[0]=n; }
            else           { tv[3]=tv[2];ti[3]=ti[2]; tv[2]=tv[1];ti[2]=ti[1]; tv[1]=v;ti[1]=n; }
        } else if (v > tv[2]) { tv[3]=tv[2];ti[3]=ti[2]; tv[2]=v;ti[2]=n; }
        else { tv[3]=v; ti[3]=n; }
    }
}
__device__ __forceinline__ void gins4(float4 v, int nb, float tv[4], int ti[4]) {
    float mx = fmaxf(fmaxf(v.x, v.y), fmaxf(v.z, v.w));
    if (mx > tv[3]) {
        ins4(v.x, nb, tv, ti); ins4(v.y, nb+1, tv, ti);
        ins4(v.z, nb+2, tv, ti); ins4(v.w, nb+3, tv, ti);
    }
}

// ---- packed fp32x2 helpers ----
__device__ __forceinline__ unsigned long long pk2(float x) {
    unsigned long long r;
    asm("mov.b64 %0, {%1, %1};" : "=l"(r) : "r"(__float_as_uint(x)));
    return r;
}
__device__ __forceinline__ unsigned long long fma2(unsigned long long a, unsigned long long b, unsigned long long c) {
    unsigned long long d;
    asm("fma.rn.f32x2 %0, %1, %2, %3;" : "=l"(d) : "l"(a), "l"(b), "l"(c));
    return d;
}
__device__ __forceinline__ float2 upk(unsigned long long v) {
    unsigned lo, hi;
    asm("mov.b64 {%0, %1}, %2;" : "=r"(lo), "=r"(hi) : "l"(v));
    return make_float2(__uint_as_float(lo), __uint_as_float(hi));
}

// ========== k0: per-point projections ==========
// dual=0: Q from src (blkoff slices grid); dual=1: K,V from tgt
__global__ __launch_bounds__(256) void k0_proj(const float* __restrict__ src, const float* __restrict__ tgt,
    const float* __restrict__ wq, const float* __restrict__ bq,
    const float* __restrict__ wk, const float* __restrict__ bk,
    const float* __restrict__ wv, const float* __restrict__ bv,
    int dual, int blkoff)
{
    __shared__ float sw1[1024], sw2[1024], sb1[32], sb2[32];
    const int tid = threadIdx.x;
    const float* in = dual ? tgt : src;
    const float* W1 = dual ? wk : wq;  const float* B1 = dual ? bk : bq;
    for (int i = tid; i < 1024; i += 256) { sw1[i] = W1[i]; if (dual) sw2[i] = wv[i]; }
    if (tid < 32) { sb1[tid] = B1[tid]; if (dual) sb2[tid] = bv[tid]; }
    __syncthreads();
    const int half = tid >> 7;
    const int p = (blockIdx.x + blkoff) * 128 + (tid & 127);
    const int b = p >> 11, pl = p & 2047;
    float* o1 = dual ? g_kt : g_qs;
    float a1[16], a2[16];
#pragma unroll
    for (int o = 0; o < 16; o++) { a1[o] = sb1[half*16+o]; a2[o] = dual ? sb2[half*16+o] : 0.f; }
#pragma unroll
    for (int i = 0; i < 32; i++) {
        float xv = in[((size_t)(b*32+i))*2048 + pl];
#pragma unroll
        for (int o = 0; o < 16; o++) {
            a1[o] += sw1[(half*16+o)*32+i] * xv;
            if (dual) a2[o] += sw2[(half*16+o)*32+i] * xv;
        }
    }
#pragma unroll
    for (int o = 0; o < 16; o++) {
        o1[(size_t)p*32 + half*16+o] = a1[o];
        if (dual) g_vt[(size_t)p*32 + half*16+o] = a2[o];
    }
}

// ========== kA: score GEMM -> g_sc (64x64 tiles, fma2) ==========
__global__ __launch_bounds__(256) void kA_gemm(const float* __restrict__ src,
                                               const float* __restrict__ tgt)
{
    __shared__ float sA[32*64], sB[32*64];
    const int b = blockIdx.z;
    const int m0 = blockIdx.y * 64, n0 = blockIdx.x * 64;
    const int tid = threadIdx.x;

    for (int i = tid; i < 512; i += 256) {
        int d = i >> 4, c = i & 15;
        ((float4*)sA)[i] = *(const float4*)(src + ((size_t)(b*32+d))*Mdim + m0 + c*4);
        ((float4*)sB)[i] = *(const float4*)(tgt + ((size_t)(b*32+d))*Ndim + n0 + c*4);
    }
    __syncthreads();

    const int tx = tid & 15, ty = tid >> 4;
    unsigned long long acc[4][2];
#pragma unroll
    for (int mi = 0; mi < 4; mi++) { acc[mi][0] = 0ull; acc[mi][1] = 0ull; }

#pragma unroll
    for (int d = 0; d < 32; d++) {
        float4 av = ((const float4*)sA)[d*16 + ty];
        ulonglong2 bv = ((const ulonglong2*)sB)[d*16 + tx];
        unsigned long long a0 = pk2(av.x), a1 = pk2(av.y), a2 = pk2(av.z), a3 = pk2(av.w);
        acc[0][0] = fma2(a0, bv.x, acc[0][0]); acc[0][1] = fma2(a0, bv.y, acc[0][1]);
        acc[1][0] = fma2(a1, bv.x, acc[1][0]); acc[1][1] = fma2(a1, bv.y, acc[1][1]);
        acc[2][0] = fma2(a2, bv.x, acc[2][0]); acc[2][1] = fma2(a2, bv.y, acc[2][1]);
        acc[3][0] = fma2(a3, bv.x, acc[3][0]); acc[3][1] = fma2(a3, bv.y, acc[3][1]);
    }
#pragma unroll
    for (int mi = 0; mi < 4; mi++) {
        float2 lo = upk(acc[mi][0]), hi = upk(acc[mi][1]);
        float4 v = make_float4(lo.x, lo.y, hi.x, hi.y);
        *(float4*)(g_sc + ((size_t)b*Mdim + m0 + ty*4 + mi)*Ndim + n0 + tx*4) = v;
    }
}

// ========== kB: copy row to smem + top-K (lane-private marks) + attention ==========
__global__ __launch_bounds__(128) void kB_topk()
{
    __shared__ float s_scores[4*2048];   // 32 KB: one score row per warp
    const int tid = threadIdx.x, b = blockIdx.y, w = tid >> 5, lane = tid & 31;
    const int m = blockIdx.x * 4 + w;
    const size_t bm = (size_t)b * Mdim + m;
    const size_t bn = (size_t)b * Ndim;
    const float4* sr4 = (const float4*)(g_sc + bm * Ndim);

    float* ws = s_scores + w*2048;
    float4* ws4 = (float4*)ws;

    float tv[4] = {-FLT_MAX,-FLT_MAX,-FLT_MAX,-FLT_MAX};
    int   ti[4] = {0x7fffffff,0x7fffffff,0x7fffffff,0x7fffffff};
#pragma unroll
    for (int j = 0; j < 16; j++) {
        float4 v = sr4[j*32 + lane];
        ws4[j*32 + lane] = v;
        gins4(v, (j*32 + lane)*4, tv, ti);
    }

    // lane-private marks -> no syncwarp needed during selection
    int nvalid = 4, nbr = 0;
    for (int it = 0; it < Kk; it++) {
        unsigned bu = __reduce_max_sync(0xffffffffu, ordf(tv[0]));
        int cand = (ordf(tv[0]) == bu) ? ti[0] : 0x7fffffff;
        int bi = __reduce_min_sync(0xffffffffu, cand);
        if (lane == it) nbr = bi;
        if (it == 0 && lane == 0) g_nn[bm] = bi;
        if (ti[0] == bi) {
            ws[bi] = -FLT_MAX;
            tv[0]=tv[1];ti[0]=ti[1]; tv[1]=tv[2];ti[1]=ti[2]; tv[2]=tv[3];ti[2]=ti[3];
            tv[3] = -FLT_MAX; ti[3] = 0x7fffffff;
            if (--nvalid == 0) {
#pragma unroll 4
                for (int j = 0; j < 16; j++) {
                    float4 v = ws4[j*32 + lane];
                    gins4(v, (j*32 + lane)*4, tv, ti);
                }
                nvalid = 4;
            }
        }
    }

    // fused attention: lane = k-index, neighbor = nbr
    const float4* q4  = (const float4*)(g_qs + bm*32);
    const float4* kk4 = (const float4*)(g_kt + (bn + nbr)*32);
    float s0=0,s1=0,s2=0,s3=0;
#pragma unroll
    for (int c = 0; c < 8; c++) {
        float4 qv = q4[c], kv = kk4[c];
        s0 += qv.x*kv.x; s1 += qv.y*kv.y; s2 += qv.z*kv.z; s3 += qv.w*kv.w;
    }
    const float sf = 0.35355339059327373f;   // 1/sqrt(8)
    s0*=sf; s1*=sf; s2*=sf; s3*=sf;
    float m0=s0,m1=s1,m2=s2,m3=s3;
#pragma unroll
    for (int o = 16; o; o >>= 1) {
        m0=fmaxf(m0,__shfl_xor_sync(0xffffffffu,m0,o));
        m1=fmaxf(m1,__shfl_xor_sync(0xffffffffu,m1,o));
        m2=fmaxf(m2,__shfl_xor_sync(0xffffffffu,m2,o));
        m3=fmaxf(m3,__shfl_xor_sync(0xffffffffu,m3,o));
    }
    float e0=expf(s0-m0), e1=expf(s1-m1), e2=expf(s2-m2), e3=expf(s3-m3);
    float z0=e0,z1=e1,z2=e2,z3=e3;
#pragma unroll
    for (int o = 16; o; o >>= 1) {
        z0+=__shfl_xor_sync(0xffffffffu,z0,o); z1+=__shfl_xor_sync(0xffffffffu,z1,o);
        z2+=__shfl_xor_sync(0xffffffffu,z2,o); z3+=__shfl_xor_sync(0xffffffffu,z3,o);
    }
    const float p0=e0/z0, p1=e1/z1, p2=e2/z2, p3=e3/z3;

    float* sT = ws;            // dead score row
    float* sP = ws + 1056;
    const float4* vv4 = (const float4*)(g_vt + (bn + nbr)*32);
#pragma unroll
    for (int c = 0; c < 8; c++) {
        float4 vv = vv4[c];
        sT[(4*c+0)*33 + lane] = vv.x;
        sT[(4*c+1)*33 + lane] = vv.y;
        sT[(4*c+2)*33 + lane] = vv.z;
        sT[(4*c+3)*33 + lane] = vv.w;
    }
    ((float4*)sP)[lane] = make_float4(p0, p1, p2, p3);
    __syncwarp();
    float acc = 0.f;
    const int r = lane & 3;
#pragma unroll
    for (int k = 0; k < 32; k++)
        acc += sP[k*4 + r] * sT[lane*33 + k];
    g_x[bm*32 + lane] = acc;
}

// ========== k2b: wm + w1 (GEMM over m, 256 threads / 8 warps) ==========
__global__ __launch_bounds__(256) void k2b_mlp(const float* __restrict__ finv, const float* __restrict__ srcf,
    const float* __restrict__ wm, const float* __restrict__ bm_,
    const float* __restrict__ w1, const float* __restrict__ b1_)
{
    __shared__ float s_wm[1024], s_w1[6144], s_bm[32], s_b1[64];
    __shared__ float s_x[32*33], s_attn[32*33];
    const int b = blockIdx.y, tid = threadIdx.x, m0 = blockIdx.x * 32;
    const int lane = tid & 31, og = tid >> 5, m = m0 + lane;   // og: 0..7

    for (int i = tid; i < 6144; i += 256) s_w1[i] = w1[i];
    for (int i = tid; i < 1024; i += 256) s_wm[i] = wm[i];
    if (tid < 64) s_b1[tid] = b1_[tid];
    if (tid < 32) s_bm[tid] = bm_[tid];
    for (int i = tid; i < 1024; i += 256) {
        int ml = i >> 5, d = i & 31;
        s_x[ml*33+d] = g_x[(((size_t)b*Mdim + m0) << 5) + i];
    }
    __syncthreads();

    float a[4];
#pragma unroll
    for (int j = 0; j < 4; j++) a[j] = s_bm[og*4+j];
#pragma unroll
    for (int i = 0; i < 32; i++) {
        float xv = s_x[lane*33+i];
#pragma unroll
        for (int j = 0; j < 4; j++) a[j] += s_wm[(og*4+j)*32+i] * xv;
    }
#pragma unroll
    for (int j = 0; j < 4; j++) {
        int o = og*4+j;
        s_attn[lane*33+o] = a[j];
        g_attn[((size_t)(b*32+o))*Mdim + m] = a[j];
    }
    __syncthreads();

    float h[8];
#pragma unroll
    for (int j = 0; j < 8; j++) h[j] = s_b1[og*8+j];
#pragma unroll
    for (int i = 0; i < 32; i++) {
        float xv = finv[((size_t)(b*32+i))*Mdim + m];
#pragma unroll
        for (int j = 0; j < 8; j++) h[j] += s_w1[(og*8+j)*96+i] * xv;
    }
#pragma unroll
    for (int i = 0; i < 32; i++) {
        float xv = srcf[((size_t)(b*32+i))*Mdim + m];
#pragma unroll
        for (int j = 0; j < 8; j++) h[j] += s_w1[(og*8+j)*96+32+i] * xv;
    }
#pragma unroll
    for (int i = 0; i < 32; i++) {
        float xv = s_attn[lane*33+i];
#pragma unroll
        for (int j = 0; j < 8; j++) h[j] += s_w1[(og*8+j)*96+64+i] * xv;
    }
#pragma unroll
    for (int j = 0; j < 8; j++)
        g_h[((size_t)(b*64 + og*8+j))*Mdim + m] = h[j];
}

// ========== k3: instance-norm stats ==========
__global__ void k3_stats()
{
    const int bc = blockIdx.x;
    const float4* row4 = (const float4*)(g_h + (size_t)bc * Mdim);
    float s = 0.f, s2 = 0.f;
    for (int i = threadIdx.x; i < Mdim/4; i += blockDim.x) {
        float4 v = row4[i];
        s  += v.x + v.y + v.z + v.w;
        s2 += v.x*v.x + v.y*v.y + v.z*v.z + v.w*v.w;
    }
    __shared__ float rs[32], rs2[32];
#pragma unroll
    for (int o = 16; o; o >>= 1) {
        s += __shfl_xor_sync(0xffffffffu, s, o);
        s2 += __shfl_xor_sync(0xffffffffu, s2, o);
    }
    if ((threadIdx.x & 31) == 0) { rs[threadIdx.x>>5] = s; rs2[threadIdx.x>>5] = s2; }
    __syncthreads();
    if (threadIdx.x == 0) {
        float S = 0, S2 = 0;
        for (int i = 0; i < (int)(blockDim.x>>5); i++) { S += rs[i]; S2 += rs2[i]; }
        float mu = S / (float)Mdim;
        float var = S2 / (float)Mdim - mu*mu;
        g_mean[bc] = mu; g_istd[bc] = rsqrtf(var + 1e-5f);
    }
}

// ========== k4: norm + relu + w2/wres (GEMM over m, 256 threads / 8 warps) ==========
__global__ __launch_bounds__(256) void k4_out(const float* __restrict__ finv, const float* __restrict__ srcf,
    const float* __restrict__ w2, const float* __restrict__ b2_,
    const float* __restrict__ wres, const float* __restrict__ bres, float* __restrict__ out)
{
    __shared__ float s_w[32*160], s_in[160*33], s_b[32];
    const int b = blockIdx.y, tid = threadIdx.x, m0 = blockIdx.x * 32;
    const int lane = tid & 31, og = tid >> 5;   // og: 0..7

    for (int i = tid; i < 5120; i += 256) {
        int o = i / 160, c = i % 160;
        s_w[i] = (c < 64) ? w2[o*64+c] : wres[o*96 + (c-64)];
    }
    if (tid < 32) s_b[tid] = b2_[tid] + bres[tid];
    for (int i = tid; i < 2048; i += 256) {
        int c = i >> 5, ml = i & 31;
        int bc = b*64 + c;
        float v = (g_h[(size_t)bc*Mdim + m0+ml] - g_mean[bc]) * g_istd[bc];
        s_in[c*33+ml] = fmaxf(v, 0.f);
    }
    for (int i = tid; i < 1024; i += 256) {
        int c = i >> 5, ml = i & 31;
        s_in[(64 +c)*33+ml] = finv[((size_t)(b*32+c))*Mdim + m0+ml];
        s_in[(96 +c)*33+ml] = srcf[((size_t)(b*32+c))*Mdim + m0+ml];
        s_in[(128+c)*33+ml] = g_attn[((size_t)(b*32+c))*Mdim + m0+ml];
    }
    __syncthreads();
    float acc[4];
#pragma unroll
    for (int j = 0; j < 4; j++) acc[j] = s_b[og*4+j];
    for (int c = 0; c < 160; c++) {
        float xv = s_in[c*33+lane];
#pragma unroll
        for (int j = 0; j < 4; j++) acc[j] += s_w[(og*4+j)*160+c] * xv;
    }
#pragma unroll
    for (int j = 0; j < 4; j++)
        out[((size_t)(b*32 + og*4+j))*Mdim + m0+lane] = acc[j];
}

// ========== k5: R_indicator — register-tiled C, perms direct from L2 ==========
__global__ __launch_bounds__(128) void k5_rind(const float* __restrict__ seqv, const float* __restrict__ teqv,
                                               const int* __restrict__ perms, float* __restrict__ out)
{
    __shared__ float s_sr[Gg*9];
    __shared__ float s_tk[8*64];
    __shared__ float s_C[Gg*65];
    __shared__ float s_red[64];
    __shared__ int s_nn[4];
    const int b = blockIdx.y, tid = threadIdx.x;
    const int w = tid >> 5, lane = tid & 31;
    const int mb = blockIdx.x * 4;

    if (tid < 4) s_nn[tid] = g_nn[(size_t)b*Mdim + mb + tid];
    __syncthreads();

    for (int rr = 0; rr < 4; rr++) {
        const int m = mb + rr;
        const int nn = s_nn[rr];
        for (int i = tid; i < Gg*8; i += 128) {
            int f = i / Gg, j = i % Gg;
            s_sr[j*9 + f]  = seqv[(((size_t)(b*8+f))*Mdim + m )*Gg + j];
            s_tk[f*64 + j] = teqv[(((size_t)(b*8+f))*Ndim + nn)*Gg + j];
        }
        __syncthreads();

        float rtk0[8], rtk1[8];
        const bool g1ok = (lane < Gg - 32);
#pragma unroll
        for (int f = 0; f < 8; f++) {
            rtk0[f] = s_tk[f*64 + lane];
            rtk1[f] = g1ok ? s_tk[f*64 + 32 + lane] : 0.f;
        }
#pragma unroll
        for (int jj = 0; jj < 15; jj++) {
            const int j = w*15 + jj;
            float a0 = 0.f, a1 = 0.f;
#pragma unroll
            for (int f = 0; f < 8; f++) {
                float sv = s_sr[j*9 + f];
                a0 += sv * rtk0[f];
                a1 += sv * rtk1[f];
            }
            s_C[j*65 + lane] = a0;
            if (g1ok) s_C[j*65 + 32 + lane] = a1;
        }
        __syncthreads();

        // gather: perms read straight from global (L2-resident, coalesced in h)
        const int h = tid & 63, halfg = tid >> 6;
        float acc = 0.f;
        if (h < Gg) {
            const int gbeg = halfg * 30;
#pragma unroll 6
            for (int g = gbeg; g < gbeg + 30; g++)
                acc += s_C[__ldg(&perms[g*Gg + h])*65 + g];
        }
        if (halfg == 1) s_red[h] = acc;
        __syncthreads();
        if (halfg == 0 && h < Gg)
            out[(size_t)Bsz*32*Mdim + ((size_t)b*Gg + h)*Mdim + m] = acc + s_red[h];
        __syncthreads();
    }
}

// ========== launch ==========
extern "C" void kernel_launch(void* const* d_in, const int* in_sizes, int n_in,
                              void* d_out, int out_size)
{
    (void)in_sizes; (void)n_in; (void)out_size;
    const float* src  = (const float*)d_in[0];
    const float* tgt  = (const float*)d_in[1];
    const float* seqv = (const float*)d_in[2];
    const float* teqv = (const float*)d_in[3];
    const float* finv = (const float*)d_in[4];
    const int*   perms = (const int*)d_in[5];
    const float* wq = (const float*)d_in[6];   const float* bq = (const float*)d_in[7];
    const float* wk = (const float*)d_in[8];   const float* bk = (const float*)d_in[9];
    const float* wv = (const float*)d_in[10];  const float* bv = (const float*)d_in[11];
    const float* wm = (const float*)d_in[12];  const float* bm = (const float*)d_in[13];
    const float* w1 = (const float*)d_in[14];  const float* b1 = (const float*)d_in[15];
    const float* w2 = (const float*)d_in[16];  const float* b2 = (const float*)d_in[17];
    const float* wres = (const float*)d_in[18]; const float* bres = (const float*)d_in[19];
    float* out = (float*)d_out;

    k0_proj<<<16, 256>>>(src, tgt, wq, bq, wk, bk, wv, bv, 0, 0);    // 1: Q half
    k0_proj<<<16, 256>>>(src, tgt, wq, bq, wk, bk, wv, bv, 0, 16);   // 2: Q half
    k0_proj<<<32, 256>>>(src, tgt, wq, bq, wk, bk, wv, bv, 1, 0);    // 3: K,V
    kA_gemm<<<dim3(32, 32, 2), 256>>>(src, tgt);                      // 4 <- profiled
    kB_topk<<<dim3(Mdim/4, Bsz), 128>>>();
    k5_rind<<<dim3(Mdim/4, Bsz), 128>>>(seqv, teqv, perms, out);
    k2b_mlp<<<dim3(Mdim/32, Bsz), 256>>>(finv, src, wm, bm, w1, b1);
    k3_stats<<<128, 256>>>();
    k4_out<<<dim3(Mdim/32, Bsz), 256>>>(finv, src, w2, b2, wres, bres, out);
}

// round 16
// speedup vs baseline: 1.0869x; 1.0869x over previous
#include <cuda_runtime.h>
#include <math.h>
#include <float.h>

#define Bsz 2
#define Mdim 2048
#define Ndim 2048
#define Kk 32
#define Gg 60

__device__ int   g_nn[Bsz * Mdim];
__device__ float g_sc[(size_t)Bsz * Mdim * Ndim];   // 33.5 MB score buffer (L2-resident)
__device__ float g_qs[Bsz * Mdim * 32];
__device__ float g_kt[Bsz * Ndim * 32];
__device__ float g_vt[Bsz * Ndim * 32];
__device__ float g_x [Bsz * Mdim * 32];
__device__ float g_attn[Bsz * 32 * Mdim];
__device__ float g_h[Bsz * 64 * Mdim];
__device__ float g_mean[Bsz * 64];
__device__ float g_istd[Bsz * 64];

__device__ __forceinline__ unsigned ordf(float f) {
    unsigned u = __float_as_uint(f);
    return (u & 0x80000000u) ? ~u : (u | 0x80000000u);
}
__device__ __forceinline__ void ins4(float v, int n, float tv[4], int ti[4]) {
    if (v > tv[3]) {
        if (v > tv[1]) {
            if (v > tv[0]) { tv[3]=tv[2];ti[3]=ti[2]; tv[2]=tv[1];ti[2]=ti[1]; tv[1]=tv[0];ti[1]=ti[0]; tv[0]=v;ti[0]=n; }
            else           { tv[3]=tv[2];ti[3]=ti[2]; tv[2]=tv[1];ti[2]=ti[1]; tv[1]=v;ti[1]=n; }
        } else if (v > tv[2]) { tv[3]=tv[2];ti[3]=ti[2]; tv[2]=v;ti[2]=n; }
        else { tv[3]=v; ti[3]=n; }
    }
}
__device__ __forceinline__ void gins4(float4 v, int nb, float tv[4], int ti[4]) {
    float mx = fmaxf(fmaxf(v.x, v.y), fmaxf(v.z, v.w));
    if (mx > tv[3]) {
        ins4(v.x, nb, tv, ti); ins4(v.y, nb+1, tv, ti);
        ins4(v.z, nb+2, tv, ti); ins4(v.w, nb+3, tv, ti);
    }
}

// ---- packed fp32x2 helpers ----
__device__ __forceinline__ unsigned long long pk2(float x) {
    unsigned long long r;
    asm("mov.b64 %0, {%1, %1};" : "=l"(r) : "r"(__float_as_uint(x)));
    return r;
}
__device__ __forceinline__ unsigned long long fma2(unsigned long long a, unsigned long long b, unsigned long long c) {
    unsigned long long d;
    asm("fma.rn.f32x2 %0, %1, %2, %3;" : "=l"(d) : "l"(a), "l"(b), "l"(c));
    return d;
}
__device__ __forceinline__ float2 upk(unsigned long long v) {
    unsigned lo, hi;
    asm("mov.b64 {%0, %1}, %2;" : "=r"(lo), "=r"(hi) : "l"(v));
    return make_float2(__uint_as_float(lo), __uint_as_float(hi));
}

// ========== k0: per-point projections (z=0: Q from src; z=1: K,V from tgt) ==========
__global__ __launch_bounds__(256) void k0_proj(const float* __restrict__ src, const float* __restrict__ tgt,
    const float* __restrict__ wq, const float* __restrict__ bq,
    const float* __restrict__ wk, const float* __restrict__ bk,
    const float* __restrict__ wv, const float* __restrict__ bv)
{
    __shared__ float sw1[1024], sw2[1024], sb1[32], sb2[32];
    const int tid = threadIdx.x;
    const int dual = blockIdx.z;
    const float* in = dual ? tgt : src;
    const float* W1 = dual ? wk : wq;  const float* B1 = dual ? bk : bq;
    for (int i = tid; i < 1024; i += 256) { sw1[i] = W1[i]; if (dual) sw2[i] = wv[i]; }
    if (tid < 32) { sb1[tid] = B1[tid]; if (dual) sb2[tid] = bv[tid]; }
    __syncthreads();
    const int half = tid >> 7;
    const int p = blockIdx.x * 128 + (tid & 127);
    const int b = p >> 11, pl = p & 2047;
    float* o1 = dual ? g_kt : g_qs;
    float a1[16], a2[16];
#pragma unroll
    for (int o = 0; o < 16; o++) { a1[o] = sb1[half*16+o]; a2[o] = dual ? sb2[half*16+o] : 0.f; }
#pragma unroll
    for (int i = 0; i < 32; i++) {
        float xv = in[((size_t)(b*32+i))*2048 + pl];
#pragma unroll
        for (int o = 0; o < 16; o++) {
            a1[o] += sw1[(half*16+o)*32+i] * xv;
            if (dual) a2[o] += sw2[(half*16+o)*32+i] * xv;
        }
    }
#pragma unroll
    for (int o = 0; o < 16; o++) {
        o1[(size_t)p*32 + half*16+o] = a1[o];
        if (dual) g_vt[(size_t)p*32 + half*16+o] = a2[o];
    }
}

// ========== kA: score GEMM -> g_sc (128x64 tiles, 8m x 4n per thread, fma2) ==========
__global__ __launch_bounds__(256) void kA_gemm(const float* __restrict__ src,
                                               const float* __restrict__ tgt, int moff)
{
    __shared__ float sA[32*128], sB[32*64];   // 16KB + 8KB
    const int b = blockIdx.z;
    const int m0 = (blockIdx.y + moff) * 128, n0 = blockIdx.x * 64;
    const int tid = threadIdx.x;

    for (int i = tid; i < 1024; i += 256) {
        int d = i >> 5, c = i & 31;
        ((float4*)sA)[i] = *(const float4*)(src + ((size_t)(b*32+d))*Mdim + m0 + c*4);
    }
    for (int i = tid; i < 512; i += 256) {
        int d = i >> 4, c = i & 15;
        ((float4*)sB)[i] = *(const float4*)(tgt + ((size_t)(b*32+d))*Ndim + n0 + c*4);
    }
    __syncthreads();

    const int tx = tid & 15, ty = tid >> 4;   // tx: n-quad, ty: m-octet
    unsigned long long acc[8][2];
#pragma unroll
    for (int mi = 0; mi < 8; mi++) { acc[mi][0] = 0ull; acc[mi][1] = 0ull; }

#pragma unroll
    for (int d = 0; d < 32; d++) {
        ulonglong2 bv = ((const ulonglong2*)sB)[d*16 + tx];
        float4 a0 = ((const float4*)sA)[d*32 + ty*2];
        float4 a1 = ((const float4*)sA)[d*32 + ty*2 + 1];
        float am[8] = {a0.x, a0.y, a0.z, a0.w, a1.x, a1.y, a1.z, a1.w};
#pragma unroll
        for (int mi = 0; mi < 8; mi++) {
            unsigned long long ap = pk2(am[mi]);
            acc[mi][0] = fma2(ap, bv.x, acc[mi][0]);
            acc[mi][1] = fma2(ap, bv.y, acc[mi][1]);
        }
    }
#pragma unroll
    for (int mi = 0; mi < 8; mi++) {
        float2 lo = upk(acc[mi][0]), hi = upk(acc[mi][1]);
        float4 v = make_float4(lo.x, lo.y, hi.x, hi.y);
        *(float4*)(g_sc + ((size_t)b*Mdim + m0 + ty*8 + mi)*Ndim + n0 + tx*4) = v;
    }
}

// ========== kB: copy row to smem + top-K (lane-private marks) + attention ==========
__global__ __launch_bounds__(128) void kB_topk()
{
    __shared__ float s_scores[4*2048];   // 32 KB: one score row per warp
    const int tid = threadIdx.x, b = blockIdx.y, w = tid >> 5, lane = tid & 31;
    const int m = blockIdx.x * 4 + w;
    const size_t bm = (size_t)b * Mdim + m;
    const size_t bn = (size_t)b * Ndim;
    const float4* sr4 = (const float4*)(g_sc + bm * Ndim);

    float* ws = s_scores + w*2048;
    float4* ws4 = (float4*)ws;

    float tv[4] = {-FLT_MAX,-FLT_MAX,-FLT_MAX,-FLT_MAX};
    int   ti[4] = {0x7fffffff,0x7fffffff,0x7fffffff,0x7fffffff};
#pragma unroll
    for (int j = 0; j < 16; j++) {
        float4 v = sr4[j*32 + lane];
        ws4[j*32 + lane] = v;
        gins4(v, (j*32 + lane)*4, tv, ti);
    }

    // lane-private marks -> no syncwarp needed during selection
    int nvalid = 4, nbr = 0;
    for (int it = 0; it < Kk; it++) {
        unsigned bu = __reduce_max_sync(0xffffffffu, ordf(tv[0]));
        int cand = (ordf(tv[0]) == bu) ? ti[0] : 0x7fffffff;
        int bi = __reduce_min_sync(0xffffffffu, cand);
        if (lane == it) nbr = bi;
        if (it == 0 && lane == 0) g_nn[bm] = bi;
        if (ti[0] == bi) {
            ws[bi] = -FLT_MAX;
            tv[0]=tv[1];ti[0]=ti[1]; tv[1]=tv[2];ti[1]=ti[2]; tv[2]=tv[3];ti[2]=ti[3];
            tv[3] = -FLT_MAX; ti[3] = 0x7fffffff;
            if (--nvalid == 0) {
#pragma unroll 4
                for (int j = 0; j < 16; j++) {
                    float4 v = ws4[j*32 + lane];
                    gins4(v, (j*32 + lane)*4, tv, ti);
                }
                nvalid = 4;
            }
        }
    }

    // fused attention: lane = k-index, neighbor = nbr
    const float4* q4  = (const float4*)(g_qs + bm*32);
    const float4* kk4 = (const float4*)(g_kt + (bn + nbr)*32);
    float s0=0,s1=0,s2=0,s3=0;
#pragma unroll
    for (int c = 0; c < 8; c++) {
        float4 qv = q4[c], kv = kk4[c];
        s0 += qv.x*kv.x; s1 += qv.y*kv.y; s2 += qv.z*kv.z; s3 += qv.w*kv.w;
    }
    const float sf = 0.35355339059327373f;   // 1/sqrt(8)
    s0*=sf; s1*=sf; s2*=sf; s3*=sf;
    float m0=s0,m1=s1,m2=s2,m3=s3;
#pragma unroll
    for (int o = 16; o; o >>= 1) {
        m0=fmaxf(m0,__shfl_xor_sync(0xffffffffu,m0,o));
        m1=fmaxf(m1,__shfl_xor_sync(0xffffffffu,m1,o));
        m2=fmaxf(m2,__shfl_xor_sync(0xffffffffu,m2,o));
        m3=fmaxf(m3,__shfl_xor_sync(0xffffffffu,m3,o));
    }
    float e0=expf(s0-m0), e1=expf(s1-m1), e2=expf(s2-m2), e3=expf(s3-m3);
    float z0=e0,z1=e1,z2=e2,z3=e3;
#pragma unroll
    for (int o = 16; o; o >>= 1) {
        z0+=__shfl_xor_sync(0xffffffffu,z0,o); z1+=__shfl_xor_sync(0xffffffffu,z1,o);
        z2+=__shfl_xor_sync(0xffffffffu,z2,o); z3+=__shfl_xor_sync(0xffffffffu,z3,o);
    }
    const float p0=e0/z0, p1=e1/z1, p2=e2/z2, p3=e3/z3;

    float* sT = ws;            // dead score row
    float* sP = ws + 1056;
    const float4* vv4 = (const float4*)(g_vt + (bn + nbr)*32);
#pragma unroll
    for (int c = 0; c < 8; c++) {
        float4 vv = vv4[c];
        sT[(4*c+0)*33 + lane] = vv.x;
        sT[(4*c+1)*33 + lane] = vv.y;
        sT[(4*c+2)*33 + lane] = vv.z;
        sT[(4*c+3)*33 + lane] = vv.w;
    }
    ((float4*)sP)[lane] = make_float4(p0, p1, p2, p3);
    __syncwarp();
    float acc = 0.f;
    const int r = lane & 3;
#pragma unroll
    for (int k = 0; k < 32; k++)
        acc += sP[k*4 + r] * sT[lane*33 + k];
    g_x[bm*32 + lane] = acc;
}

// ========== k2b: wm + w1 (GEMM over m, 256 threads / 8 warps) ==========
__global__ __launch_bounds__(256) void k2b_mlp(const float* __restrict__ finv, const float* __restrict__ srcf,
    const float* __restrict__ wm, const float* __restrict__ bm_,
    const float* __restrict__ w1, const float* __restrict__ b1_)
{
    __shared__ float s_wm[1024], s_w1[6144], s_bm[32], s_b1[64];
    __shared__ float s_x[32*33], s_attn[32*33];
    const int b = blockIdx.y, tid = threadIdx.x, m0 = blockIdx.x * 32;
    const int lane = tid & 31, og = tid >> 5, m = m0 + lane;   // og: 0..7

    for (int i = tid; i < 6144; i += 256) s_w1[i] = w1[i];
    for (int i = tid; i < 1024; i += 256) s_wm[i] = wm[i];
    if (tid < 64) s_b1[tid] = b1_[tid];
    if (tid < 32) s_bm[tid] = bm_[tid];
    for (int i = tid; i < 1024; i += 256) {
        int ml = i >> 5, d = i & 31;
        s_x[ml*33+d] = g_x[(((size_t)b*Mdim + m0) << 5) + i];
    }
    __syncthreads();

    float a[4];
#pragma unroll
    for (int j = 0; j < 4; j++) a[j] = s_bm[og*4+j];
#pragma unroll
    for (int i = 0; i < 32; i++) {
        float xv = s_x[lane*33+i];
#pragma unroll
        for (int j = 0; j < 4; j++) a[j] += s_wm[(og*4+j)*32+i] * xv;
    }
#pragma unroll
    for (int j = 0; j < 4; j++) {
        int o = og*4+j;
        s_attn[lane*33+o] = a[j];
        g_attn[((size_t)(b*32+o))*Mdim + m] = a[j];
    }
    __syncthreads();

    float h[8];
#pragma unroll
    for (int j = 0; j < 8; j++) h[j] = s_b1[og*8+j];
#pragma unroll
    for (int i = 0; i < 32; i++) {
        float xv = finv[((size_t)(b*32+i))*Mdim + m];
#pragma unroll
        for (int j = 0; j < 8; j++) h[j] += s_w1[(og*8+j)*96+i] * xv;
    }
#pragma unroll
    for (int i = 0; i < 32; i++) {
        float xv = srcf[((size_t)(b*32+i))*Mdim + m];
#pragma unroll
        for (int j = 0; j < 8; j++) h[j] += s_w1[(og*8+j)*96+32+i] * xv;
    }
#pragma unroll
    for (int i = 0; i < 32; i++) {
        float xv = s_attn[lane*33+i];
#pragma unroll
        for (int j = 0; j < 8; j++) h[j] += s_w1[(og*8+j)*96+64+i] * xv;
    }
#pragma unroll
    for (int j = 0; j < 8; j++)
        g_h[((size_t)(b*64 + og*8+j))*Mdim + m] = h[j];
}

// ========== k3: instance-norm stats ==========
__global__ void k3_stats()
{
    const int bc = blockIdx.x;
    const float4* row4 = (const float4*)(g_h + (size_t)bc * Mdim);
    float s = 0.f, s2 = 0.f;
    for (int i = threadIdx.x; i < Mdim/4; i += blockDim.x) {
        float4 v = row4[i];
        s  += v.x + v.y + v.z + v.w;
        s2 += v.x*v.x + v.y*v.y + v.z*v.z + v.w*v.w;
    }
    __shared__ float rs[32], rs2[32];
#pragma unroll
    for (int o = 16; o; o >>= 1) {
        s += __shfl_xor_sync(0xffffffffu, s, o);
        s2 += __shfl_xor_sync(0xffffffffu, s2, o);
    }
    if ((threadIdx.x & 31) == 0) { rs[threadIdx.x>>5] = s; rs2[threadIdx.x>>5] = s2; }
    __syncthreads();
    if (threadIdx.x == 0) {
        float S = 0, S2 = 0;
        for (int i = 0; i < (int)(blockDim.x>>5); i++) { S += rs[i]; S2 += rs2[i]; }
        float mu = S / (float)Mdim;
        float var = S2 / (float)Mdim - mu*mu;
        g_mean[bc] = mu; g_istd[bc] = rsqrtf(var + 1e-5f);
    }
}

// ========== k4: norm + relu + w2/wres (GEMM over m, 256 threads / 8 warps) ==========
__global__ __launch_bounds__(256) void k4_out(const float* __restrict__ finv, const float* __restrict__ srcf,
    const float* __restrict__ w2, const float* __restrict__ b2_,
    const float* __restrict__ wres, const float* __restrict__ bres, float* __restrict__ out)
{
    __shared__ float s_w[32*160], s_in[160*33], s_b[32];
    const int b = blockIdx.y, tid = threadIdx.x, m0 = blockIdx.x * 32;
    const int lane = tid & 31, og = tid >> 5;   // og: 0..7

    for (int i = tid; i < 5120; i += 256) {
        int o = i / 160, c = i % 160;
        s_w[i] = (c < 64) ? w2[o*64+c] : wres[o*96 + (c-64)];
    }
    if (tid < 32) s_b[tid] = b2_[tid] + bres[tid];
    for (int i = tid; i < 2048; i += 256) {
        int c = i >> 5, ml = i & 31;
        int bc = b*64 + c;
        float v = (g_h[(size_t)bc*Mdim + m0+ml] - g_mean[bc]) * g_istd[bc];
        s_in[c*33+ml] = fmaxf(v, 0.f);
    }
    for (int i = tid; i < 1024; i += 256) {
        int c = i >> 5, ml = i & 31;
        s_in[(64 +c)*33+ml] = finv[((size_t)(b*32+c))*Mdim + m0+ml];
        s_in[(96 +c)*33+ml] = srcf[((size_t)(b*32+c))*Mdim + m0+ml];
        s_in[(128+c)*33+ml] = g_attn[((size_t)(b*32+c))*Mdim + m0+ml];
    }
    __syncthreads();
    float acc[4];
#pragma unroll
    for (int j = 0; j < 4; j++) acc[j] = s_b[og*4+j];
    for (int c = 0; c < 160; c++) {
        float xv = s_in[c*33+lane];
#pragma unroll
        for (int j = 0; j < 4; j++) acc[j] += s_w[(og*4+j)*160+c] * xv;
    }
#pragma unroll
    for (int j = 0; j < 4; j++)
        out[((size_t)(b*32 + og*4+j))*Mdim + m0+lane] = acc[j];
}

// ========== k5: R_indicator — register-tiled C, smem perms, 4 m per block ==========
__global__ __launch_bounds__(128) void k5_rind(const float* __restrict__ seqv, const float* __restrict__ teqv,
                                               const int* __restrict__ perms, float* __restrict__ out)
{
    __shared__ int   s_p[Gg*Gg];
    __shared__ float s_sr[Gg*9];
    __shared__ float s_tk[8*64];
    __shared__ float s_C[Gg*65];
    __shared__ float s_red[64];
    __shared__ int s_nn[4];
    const int b = blockIdx.y, tid = threadIdx.x;
    const int w = tid >> 5, lane = tid & 31;
    const int mb = blockIdx.x * 4;

    for (int i = tid; i < Gg*Gg; i += 128) s_p[i] = perms[i];
    if (tid < 4) s_nn[tid] = g_nn[(size_t)b*Mdim + mb + tid];
    __syncthreads();

    for (int rr = 0; rr < 4; rr++) {
        const int m = mb + rr;
        const int nn = s_nn[rr];
        for (int i = tid; i < Gg*8; i += 128) {
            int f = i / Gg, j = i % Gg;
            s_sr[j*9 + f]  = seqv[(((size_t)(b*8+f))*Mdim + m )*Gg + j];
            s_tk[f*64 + j] = teqv[(((size_t)(b*8+f))*Ndim + nn)*Gg + j];
        }
        __syncthreads();

        float rtk0[8], rtk1[8];
        const bool g1ok = (lane < Gg - 32);
#pragma unroll
        for (int f = 0; f < 8; f++) {
            rtk0[f] = s_tk[f*64 + lane];
            rtk1[f] = g1ok ? s_tk[f*64 + 32 + lane] : 0.f;
        }
#pragma unroll
        for (int jj = 0; jj < 15; jj++) {
            const int j = w*15 + jj;
            float a0 = 0.f, a1 = 0.f;
#pragma unroll
            for (int f = 0; f < 8; f++) {
                float sv = s_sr[j*9 + f];
                a0 += sv * rtk0[f];
                a1 += sv * rtk1[f];
            }
            s_C[j*65 + lane] = a0;
            if (g1ok) s_C[j*65 + 32 + lane] = a1;
        }
        __syncthreads();

        const int h = tid & 63, halfg = tid >> 6;
        float acc = 0.f;
        if (h < Gg) {
            const int gbeg = halfg * 30;
#pragma unroll 6
            for (int g = gbeg; g < gbeg + 30; g++)
                acc += s_C[s_p[g*Gg + h]*65 + g];
        }
        if (halfg == 1) s_red[h] = acc;
        __syncthreads();
        if (halfg == 0 && h < Gg)
            out[(size_t)Bsz*32*Mdim + ((size_t)b*Gg + h)*Mdim + m] = acc + s_red[h];
        __syncthreads();
    }
}

// ========== launch ==========
extern "C" void kernel_launch(void* const* d_in, const int* in_sizes, int n_in,
                              void* d_out, int out_size)
{
    (void)in_sizes; (void)n_in; (void)out_size;
    const float* src  = (const float*)d_in[0];
    const float* tgt  = (const float*)d_in[1];
    const float* seqv = (const float*)d_in[2];
    const float* teqv = (const float*)d_in[3];
    const float* finv = (const float*)d_in[4];
    const int*   perms = (const int*)d_in[5];
    const float* wq = (const float*)d_in[6];   const float* bq = (const float*)d_in[7];
    const float* wk = (const float*)d_in[8];   const float* bk = (const float*)d_in[9];
    const float* wv = (const float*)d_in[10];  const float* bv = (const float*)d_in[11];
    const float* wm = (const float*)d_in[12];  const float* bm = (const float*)d_in[13];
    const float* w1 = (const float*)d_in[14];  const float* b1 = (const float*)d_in[15];
    const float* w2 = (const float*)d_in[16];  const float* b2 = (const float*)d_in[17];
    const float* wres = (const float*)d_in[18]; const float* bres = (const float*)d_in[19];
    float* out = (float*)d_out;

    k0_proj<<<dim3(32, 1, 2), 256>>>(src, tgt, wq, bq, wk, bk, wv, bv);   // 1
    kA_gemm<<<dim3(32, 8, 2), 256>>>(src, tgt, 0);                         // 2: m-tiles 0..7
    kA_gemm<<<dim3(32, 8, 2), 256>>>(src, tgt, 8);                         // 3: m-tiles 8..15
    kB_topk<<<dim3(Mdim/4, Bsz), 128>>>();                                 // 4 <- profiled
    k5_rind<<<dim3(Mdim/4, Bsz), 128>>>(seqv, teqv, perms, out);
    k2b_mlp<<<dim3(Mdim/32, Bsz), 256>>>(finv, src, wm, bm, w1, b1);
    k3_stats<<<128, 256>>>();
    k4_out<<<dim3(Mdim/32, Bsz), 256>>>(finv, src, w2, b2, wres, bres, out);
}